// round 9
// baseline (speedup 1.0000x reference)
#include <cuda_runtime.h>
#include <cuda_bf16.h>
#include <mma.h>
#include <cstdint>

using namespace nvcuda;

#define BATCH 32768
#define DIN   768
#define DHID  2048
#define TOPK  32

// -------- scratch (no cudaMalloc allowed) --------
__device__ __align__(16) float g_Wt[(size_t)DHID * DIN];   // W_dec^T [2048][768]
__device__ int   g_tidx[(size_t)BATCH * TOPK];
__device__ float g_tval[(size_t)BATCH * TOPK];
__device__ __align__(16) __nv_bfloat16 g_Ah[(size_t)BATCH * DIN];
__device__ __align__(16) __nv_bfloat16 g_Al[(size_t)BATCH * DIN];
__device__ __align__(16) __nv_bfloat16 g_Bh[(size_t)DHID * DIN];
__device__ __align__(16) __nv_bfloat16 g_Bl[(size_t)DHID * DIN];

// ============================================================
// f32 -> (hi, lo) bf16 split
// ============================================================
__global__ __launch_bounds__(256)
void split_kernel(const float* __restrict__ src,
                  __nv_bfloat16* __restrict__ hi,
                  __nv_bfloat16* __restrict__ lo)
{
    int i = blockIdx.x * 256 + threadIdx.x;
    float2 v = ((const float2*)src)[i];
    __nv_bfloat16 h0 = __float2bfloat16(v.x);
    __nv_bfloat16 h1 = __float2bfloat16(v.y);
    __nv_bfloat16 l0 = __float2bfloat16(v.x - __bfloat162float(h0));
    __nv_bfloat16 l1 = __float2bfloat16(v.y - __bfloat162float(h1));
    ((__nv_bfloat162*)hi)[i] = __halves2bfloat162(h0, h1);
    ((__nv_bfloat162*)lo)[i] = __halves2bfloat162(l0, l1);
}

// ============================================================
// W_dec [768][2048] -> g_Wt [2048][768]
// ============================================================
__global__ void transpose_kernel(const float* __restrict__ W)
{
    __shared__ float tile[32][33];
    int bx = blockIdx.x * 32, by = blockIdx.y * 32;
    int tx = threadIdx.x, ty = threadIdx.y;
#pragma unroll
    for (int i = 0; i < 32; i += 8)
        tile[ty + i][tx] = W[(size_t)(by + ty + i) * DHID + bx + tx];
    __syncthreads();
#pragma unroll
    for (int i = 0; i < 32; i += 8)
        g_Wt[(size_t)(bx + ty + i) * DIN + by + tx] = tile[tx][ty + i];
}

// ============================================================
// Encoder GEMM, bf16 3-split, cp.async, 2 CTAs/SM.
// BK=48 (16 k-tiles), ONE __syncthreads per k-tile:
//   wait_group 0 -> sync -> issue load(t+1) -> compute(t)
// ============================================================
#define BK     48
#define HS     56                       // halves per row (48 + 8 pad, 112B)
#define PART   (128 * HS)               // halves per matrix part
#define STG_H  (4 * PART)               // halves per stage
#define NKT    (DIN / BK)               // 16
#define GEMM_SMEM (2 * STG_H * sizeof(__nv_bfloat16))   // 114688 B

__device__ __forceinline__ void cp16(__nv_bfloat16* dst, const __nv_bfloat16* src)
{
    unsigned d = (unsigned)__cvta_generic_to_shared(dst);
    asm volatile("cp.async.cg.shared.global [%0], [%1], 16;\n" :: "r"(d), "l"(src));
}

__global__ __launch_bounds__(256, 2)
void gemm_bf16x3(const float* __restrict__ bias, float* __restrict__ C)
{
    extern __shared__ __nv_bfloat16 smh[];   // 2 stages

    int tid  = threadIdx.x;
    int warp = tid >> 5;
    int wm   = warp & 3;
    int wn   = warp >> 2;
    int m0 = blockIdx.y * 128;
    int n0 = blockIdx.x * 128;

    using FragA = wmma::fragment<wmma::matrix_a, 16, 16, 16, __nv_bfloat16, wmma::row_major>;
    using FragB = wmma::fragment<wmma::matrix_b, 16, 16, 16, __nv_bfloat16, wmma::col_major>;
    using FragC = wmma::fragment<wmma::accumulator, 16, 16, 16, float>;

    // ---- bias init via smem f32 broadcast tile (reuses stage region) ----
    float* bsm = (float*)smh;
    for (int i = tid; i < 16 * 128; i += 256)
        bsm[i] = bias[n0 + (i & 127)];
    __syncthreads();

    FragC acc[2][4];
#pragma unroll
    for (int i = 0; i < 2; i++)
#pragma unroll
        for (int j = 0; j < 4; j++)
            wmma::load_matrix_sync(acc[i][j], &bsm[wn * 64 + j * 16], 128, wmma::mem_row_major);
    __syncthreads();

    // per part: 128 rows x 48 halves = 768 cp16 = 3 per thread
    auto load_tile = [&](int buf, int kt) {
        __nv_bfloat16* s = smh + buf * STG_H;
        int k0 = kt * BK;
#pragma unroll
        for (int p = 0; p < 3; p++) {
            int f  = tid + p * 256;      // 0..767
            int r  = f / 6;              // 0..127
            int ch = (f % 6) * 8;        // halves offset 0..40
            size_t ga = (size_t)(m0 + r) * DIN + k0 + ch;
            size_t gb = (size_t)(n0 + r) * DIN + k0 + ch;
            cp16(&s[0 * PART + r * HS + ch], &g_Ah[ga]);
            cp16(&s[1 * PART + r * HS + ch], &g_Al[ga]);
            cp16(&s[2 * PART + r * HS + ch], &g_Bh[gb]);
            cp16(&s[3 * PART + r * HS + ch], &g_Bl[gb]);
        }
        asm volatile("cp.async.commit_group;\n" ::);
    };

    load_tile(0, 0);

    for (int t = 0; t < NKT; t++) {
        asm volatile("cp.async.wait_group 0;\n" ::);
        __syncthreads();                      // tile t visible; compute t-1 done

        if (t + 1 < NKT) load_tile((t + 1) & 1, t + 1);

        __nv_bfloat16* s  = smh + (t & 1) * STG_H;
        __nv_bfloat16* Ah = s;
        __nv_bfloat16* Al = s + PART;
        __nv_bfloat16* Bh = s + 2 * PART;
        __nv_bfloat16* Bl = s + 3 * PART;

#pragma unroll
        for (int ks = 0; ks < BK; ks += 16) {
            FragA ah[2], al[2];
            FragB bh[4];
#pragma unroll
            for (int i = 0; i < 2; i++) {
                wmma::load_matrix_sync(ah[i], &Ah[(wm * 32 + i * 16) * HS + ks], HS);
                wmma::load_matrix_sync(al[i], &Al[(wm * 32 + i * 16) * HS + ks], HS);
            }
#pragma unroll
            for (int j = 0; j < 4; j++)
                wmma::load_matrix_sync(bh[j], &Bh[(wn * 64 + j * 16) * HS + ks], HS);

#pragma unroll
            for (int j = 0; j < 4; j++)
#pragma unroll
                for (int i = 0; i < 2; i++)
                    wmma::mma_sync(acc[i][j], ah[i], bh[j], acc[i][j]);

#pragma unroll
            for (int j = 0; j < 4; j++) {
                FragB bl;
                wmma::load_matrix_sync(bl, &Bl[(wn * 64 + j * 16) * HS + ks], HS);
#pragma unroll
                for (int i = 0; i < 2; i++)
                    wmma::mma_sync(acc[i][j], ah[i], bl, acc[i][j]);
            }

#pragma unroll
            for (int j = 0; j < 4; j++)
#pragma unroll
                for (int i = 0; i < 2; i++)
                    wmma::mma_sync(acc[i][j], al[i], bh[j], acc[i][j]);
        }
    }

#pragma unroll
    for (int i = 0; i < 2; i++)
#pragma unroll
        for (int j = 0; j < 4; j++) {
            float* cp = &C[(size_t)(m0 + wm * 32 + i * 16) * DHID + n0 + wn * 64 + j * 16];
            wmma::store_matrix_sync(cp, acc[i][j], DHID, wmma::mem_row_major);
        }
}

// ============================================================
// Top-K with exact fp64 re-ranking of the ambiguous boundary.
// ============================================================
#define AMBIG_W 1e-4f
#define MAXCAND 16

__device__ __forceinline__ float key_decode(unsigned k)
{
    return (k >= 0x80000000u) ? __uint_as_float(k ^ 0x80000000u)
                              : __uint_as_float(~k);
}

__global__ __launch_bounds__(256)
void topk_kernel(const float* __restrict__ hpre, float* __restrict__ hsp,
                 const float* __restrict__ x, const float* __restrict__ Wenc)
{
    int lane = threadIdx.x & 31;
    int warp = threadIdx.x >> 5;
    int row  = blockIdx.x * 8 + warp;
    const float* p = hpre + (size_t)row * DHID;

    __shared__ int    s_cidx[8][MAXCAND];
    __shared__ double s_cval[8][MAXCAND];
    __shared__ int    s_csel[8][MAXCAND];
    __shared__ unsigned s_chosen[8];

    unsigned key[64];
#pragma unroll
    for (int j = 0; j < 64; j++) {
        unsigned u = __float_as_uint(p[j * 32 + lane]);
        key[j] = (u & 0x80000000u) ? ~u : (u | 0x80000000u);
    }

    unsigned lmax = 0u;
#pragma unroll
    for (int j = 0; j < 64; j++) lmax = (key[j] > lmax) ? key[j] : lmax;
    unsigned lo = __reduce_min_sync(0xFFFFFFFFu, lmax);
    unsigned hi = __reduce_max_sync(0xFFFFFFFFu, lmax);

#pragma unroll 1
    for (int it = 0; it < 32; ++it) {
        if (lo >= hi) break;
        unsigned span = hi - lo;
        unsigned mid = lo + (span >> 1) + (span & 1u);
        int c = 0;
#pragma unroll
        for (int j = 0; j < 64; j++) c += (key[j] >= mid) ? 1 : 0;
        c = __reduce_add_sync(0xFFFFFFFFu, c);
        if (c >= TOPK) lo = mid; else hi = mid - 1;
    }
    unsigned T = lo;

    int cg = 0;
#pragma unroll
    for (int j = 0; j < 64; j++) cg += (key[j] > T) ? 1 : 0;
    cg = __reduce_add_sync(0xFFFFFFFFu, cg);
    int rem = TOPK - cg;

    unsigned lmask = (1u << lane) - 1u;
    unsigned long long selmask = 0ull;
    unsigned kmin_in = 0xFFFFFFFFu;
    unsigned kmax_out = 0u;
#pragma unroll 1
    for (int j = 0; j < 64; j++) {
        unsigned k = key[j];
        bool eq = (k == T);
        unsigned em = __ballot_sync(0xFFFFFFFFu, eq);
        bool pick = eq && ((int)__popc(em & lmask) < rem);
        bool sel  = (k > T) || pick;
        if (sel) { selmask |= (1ull << j); if (k < kmin_in) kmin_in = k; }
        else     { if (k > kmax_out) kmax_out = k; }
        rem -= __popc(em);
        if (rem < 0) rem = 0;
    }
    kmin_in  = __reduce_min_sync(0xFFFFFFFFu, kmin_in);
    kmax_out = __reduce_max_sync(0xFFFFFFFFu, kmax_out);

    float vin  = key_decode(kmin_in);
    float vout = key_decode(kmax_out);

    if (vin - vout < AMBIG_W) {
        float wlo = vout - AMBIG_W;
        float whi = vin + AMBIG_W;
        int ncand = 0;
#pragma unroll 1
        for (int j = 0; j < 64; j++) {
            float v = key_decode(key[j]);
            bool isc = (v >= wlo) && (v <= whi);
            unsigned bal = __ballot_sync(0xFFFFFFFFu, isc);
            if (isc) {
                int pos = ncand + __popc(bal & lmask);
                if (pos < MAXCAND) {
                    s_cidx[warp][pos] = j * 32 + lane;
                    s_csel[warp][pos] = (int)((selmask >> j) & 1ull);
                }
            }
            ncand += __popc(bal);
        }
        if (ncand > MAXCAND) ncand = MAXCAND;
        __syncwarp();

        const float* xr = x + (size_t)row * DIN;
        for (int c = 0; c < ncand; c++) {
            const float* wr = Wenc + (size_t)s_cidx[warp][c] * DIN;
            double s = 0.0;
#pragma unroll
            for (int t = 0; t < DIN / 32; t++) {
                int kk = lane + t * 32;
                s += (double)xr[kk] * (double)wr[kk];
            }
#pragma unroll
            for (int off = 16; off > 0; off >>= 1)
                s += __shfl_down_sync(0xFFFFFFFFu, s, off);
            if (lane == 0) s_cval[warp][c] = s;
            __syncwarp();
        }

        if (lane == 0) {
            int nkeep = 0;
            for (int c = 0; c < ncand; c++) nkeep += s_csel[warp][c];
            unsigned chosen = 0;
            for (int s = 0; s < nkeep; s++) {
                int best = -1;
                for (int c = 0; c < ncand; c++) {
                    if (chosen & (1u << c)) continue;
                    if (best < 0 ||
                        s_cval[warp][c] > s_cval[warp][best] ||
                        (s_cval[warp][c] == s_cval[warp][best] &&
                         s_cidx[warp][c] < s_cidx[warp][best]))
                        best = c;
                }
                chosen |= (1u << best);
            }
            s_chosen[warp] = chosen;
        }
        __syncwarp();
        unsigned chosen = s_chosen[warp];

        for (int c = 0; c < ncand; c++) {
            int fi = s_cidx[warp][c];
            if ((fi & 31) == lane) {
                int j = fi >> 5;
                if (chosen & (1u << c)) selmask |=  (1ull << j);
                else                    selmask &= ~(1ull << j);
            }
        }
        __syncwarp();
    }

    float* orow = hsp + (size_t)row * DHID;
    int nsel = 0;
#pragma unroll 1
    for (int j = 0; j < 64; j++) {
        bool sel = (selmask >> j) & 1ull;
        unsigned k = key[j];
        float v = (k > 0x80000000u) ? __uint_as_float(k ^ 0x80000000u) : 0.0f;
        orow[j * 32 + lane] = sel ? v : 0.0f;

        unsigned sm2 = __ballot_sync(0xFFFFFFFFu, sel);
        if (sel) {
            int slot = nsel + __popc(sm2 & lmask);
            g_tidx[(size_t)row * TOPK + slot] = j * 32 + lane;
            g_tval[(size_t)row * TOPK + slot] = v;
        }
        nsel += __popc(sm2);
    }
}

// ============================================================
// Sparse decoder: recon[row,:] = b_dec + sum_k val_k * Wt[idx_k,:]
// ============================================================
__global__ __launch_bounds__(192)
void decode_kernel(const float* __restrict__ bdec, float* __restrict__ recon)
{
    int row = blockIdx.x;
    int t = threadIdx.x;
    __shared__ float sval[TOPK];
    __shared__ int   sidx[TOPK];
    if (t < TOPK) {
        sval[t] = g_tval[(size_t)row * TOPK + t];
        sidx[t] = g_tidx[(size_t)row * TOPK + t];
    }
    __syncthreads();

    float4 acc = *(const float4*)&bdec[t * 4];
#pragma unroll 8
    for (int k = 0; k < TOPK; k++) {
        float v = sval[k];
        float4 w = *(const float4*)&g_Wt[(size_t)sidx[k] * DIN + t * 4];
        acc.x += v * w.x; acc.y += v * w.y; acc.z += v * w.z; acc.w += v * w.w;
    }
    *(float4*)&recon[(size_t)row * DIN + t * 4] = acc;
}

// ============================================================
extern "C" void kernel_launch(void* const* d_in, const int* in_sizes, int n_in,
                              void* d_out, int out_size)
{
    const float* x     = (const float*)d_in[0];
    const float* W_enc = (const float*)d_in[1];
    const float* b_enc = (const float*)d_in[2];
    const float* W_dec = (const float*)d_in[3];
    const float* b_dec = (const float*)d_in[4];

    float* out   = (float*)d_out;
    float* recon = out;                                 // [B, 768]
    float* hsp   = out + (size_t)BATCH * DIN;           // [B, 2048]
    float* hpre  = hsp + (size_t)BATCH * DHID;          // [B, 2048]

    __nv_bfloat16 *ah, *al, *bh, *bl;
    cudaGetSymbolAddress((void**)&ah, g_Ah);
    cudaGetSymbolAddress((void**)&al, g_Al);
    cudaGetSymbolAddress((void**)&bh, g_Bh);
    cudaGetSymbolAddress((void**)&bl, g_Bl);

    cudaFuncSetAttribute(gemm_bf16x3, cudaFuncAttributeMaxDynamicSharedMemorySize,
                         (int)GEMM_SMEM);

    split_kernel<<<(BATCH * DIN / 2) / 256, 256>>>(x, ah, al);
    split_kernel<<<(DHID * DIN / 2) / 256, 256>>>(W_enc, bh, bl);
    transpose_kernel<<<dim3(DHID / 32, DIN / 32), dim3(32, 8)>>>(W_dec);
    gemm_bf16x3<<<dim3(DHID / 128, BATCH / 128), 256, GEMM_SMEM>>>(b_enc, hpre);
    topk_kernel<<<BATCH / 8, 256>>>(hpre, hsp, x, W_enc);
    decode_kernel<<<BATCH, 192>>>(b_dec, recon);
}